// round 9
// baseline (speedup 1.0000x reference)
#include <cuda_runtime.h>

// Problem constants
#define VOCAB 50257
#define EMB   128
#define MEM   256   // memory slots (M)
#define BATCH 16    // batch (B)
#define SENT  64    // sentence length (S)
#define TBL   ((size_t)VOCAB * EMB)
#define FULLMASK 0xffffffffu

// Scratch (static, no allocation):
//  g_wt[0][v][b]: token counts per (batch, vocab)  (float; exact for small ints)
//  g_wt[1][v][b]: w1 = scattered prob1             g_wt[2]: w2 = scattered prob2
//  g_d[v][b]   : per-token dot with current state  (only written where cnt>0)
//  g_acc[0]=u1_raw (256x u1), g_acc[1]=o1, g_acc[2]=o2   each [BATCH*EMB]
__device__ __align__(16) float g_wt[3][VOCAB][16];
__device__ __align__(16) float g_d[VOCAB][16];
__device__ __align__(16) float g_acc[3][BATCH * EMB];

// ---------------------------------------------------------------------------
// L0a: zero the weight tables and accumulators (every launch).
// ---------------------------------------------------------------------------
__global__ void __launch_bounds__(256) zero_kernel() {
    const int N1 = (3 * VOCAB * 16) / 4;        // 603084 float4
    int i = blockIdx.x * 256 + threadIdx.x;
    float4 z = make_float4(0.f, 0.f, 0.f, 0.f);
    if (i < N1) ((float4*)g_wt)[i] = z;
    if (i < (3 * BATCH * EMB) / 4) ((float4*)g_acc)[i] = z;
}

// ---------------------------------------------------------------------------
// L0b: token-count histogram cnt[b][tok] from story.
// story layout (M, B, S): idx = m*1024 + b*64 + s  ->  b = (idx>>6)&15
// ---------------------------------------------------------------------------
__global__ void __launch_bounds__(256) cnt_kernel(const int* __restrict__ story) {
    int idx = blockIdx.x * 256 + threadIdx.x;   // exactly 262144 threads
    int tok = story[idx];
    int b = (idx >> 6) & 15;
    atomicAdd(&g_wt[0][tok][b], 1.0f);
}

// ---------------------------------------------------------------------------
// scan_w: acc[ai][b][:] += sum_v wt[wi][v][b] * tab[v][:]
// Warp per 2 rows (grid-stride). Lane holds a float4 slice of the row; weights
// broadcast by shuffle; skip zero weights (~72% of (b,v) pairs).
// ---------------------------------------------------------------------------
__global__ void __launch_bounds__(256) scan_w(const float* __restrict__ tab,
                                              int wi, int ai) {
    const int wid = threadIdx.x >> 5, lane = threadIdx.x & 31;
    const int gw = blockIdx.x * 8 + wid, nw = gridDim.x * 8;
    const float4* __restrict__ t4 = (const float4*)tab;

    float4 acc[16];
#pragma unroll
    for (int b = 0; b < 16; b++) acc[b] = make_float4(0.f, 0.f, 0.f, 0.f);

    for (int p = gw; 2 * p < VOCAB; p += nw) {
        const int v0 = 2 * p, v1 = v0 + 1;
        const bool has1 = (v1 < VOCAB);
        float4 r0 = __ldg(t4 + (size_t)v0 * 32 + lane);
        float4 r1 = has1 ? __ldg(t4 + (size_t)v1 * 32 + lane)
                         : make_float4(0.f, 0.f, 0.f, 0.f);
        float w0 = (lane < 16) ? g_wt[wi][v0][lane] : 0.f;
        float w1 = (lane < 16 && has1) ? g_wt[wi][v1][lane] : 0.f;
#pragma unroll
        for (int b = 0; b < 16; b++) {
            float c0 = __shfl_sync(FULLMASK, w0, b);
            float c1 = __shfl_sync(FULLMASK, w1, b);
            if (c0 != 0.f) {
                acc[b].x += c0 * r0.x; acc[b].y += c0 * r0.y;
                acc[b].z += c0 * r0.z; acc[b].w += c0 * r0.w;
            }
            if (c1 != 0.f) {
                acc[b].x += c1 * r1.x; acc[b].y += c1 * r1.y;
                acc[b].z += c1 * r1.z; acc[b].w += c1 * r1.w;
            }
        }
    }

    // block-level reduction in two 8-b rounds (32 KB smem), then atomics
    __shared__ float4 sred[8][8][32];
#pragma unroll
    for (int r = 0; r < 2; r++) {
#pragma unroll
        for (int i = 0; i < 8; i++) sred[wid][i][lane] = acc[r * 8 + i];
        __syncthreads();
        {
            const int bi = threadIdx.x >> 5, ln = threadIdx.x & 31;
            float4 s = sred[0][bi][ln];
#pragma unroll
            for (int k = 1; k < 8; k++) {
                float4 c = sred[k][bi][ln];
                s.x += c.x; s.y += c.y; s.z += c.z; s.w += c.w;
            }
            float* dst = &g_acc[ai][(r * 8 + bi) * EMB + ln * 4];
            atomicAdd(dst + 0, s.x); atomicAdd(dst + 1, s.y);
            atomicAdd(dst + 2, s.z); atomicAdd(dst + 3, s.w);
        }
        __syncthreads();
    }
}

// ---------------------------------------------------------------------------
// scan_d: g_d[v][b] = dot(tab[v], u[b]) for (b,v) with cnt>0.
//   mode 0: u = u1 = acc0/256        mode 1: u = u2 = acc0/256 + acc1
// Warp per 2 rows; high grid (8 CTAs/SM) to hide the shuffle-reduce chains.
// ---------------------------------------------------------------------------
__global__ void __launch_bounds__(256) scan_d(const float* __restrict__ tab,
                                              int mode) {
    __shared__ float4 us4[512];     // u for all 16 b: us4[b*32 + k]
    for (int i = threadIdx.x; i < 512; i += 256) {
        float4 a = ((const float4*)g_acc[0])[i];
        a.x *= (1.f / 256.f); a.y *= (1.f / 256.f);
        a.z *= (1.f / 256.f); a.w *= (1.f / 256.f);
        if (mode) {
            float4 o = ((const float4*)g_acc[1])[i];
            a.x += o.x; a.y += o.y; a.z += o.z; a.w += o.w;
        }
        us4[i] = a;
    }
    __syncthreads();

    const int wid = threadIdx.x >> 5, lane = threadIdx.x & 31;
    const int gw = blockIdx.x * 8 + wid, nw = gridDim.x * 8;
    const float4* __restrict__ t4 = (const float4*)tab;

    for (int p = gw; 2 * p < VOCAB; p += nw) {
        const int v0 = 2 * p, v1 = v0 + 1;
        const bool has1 = (v1 < VOCAB);
        float4 r0 = __ldg(t4 + (size_t)v0 * 32 + lane);
        float4 r1 = has1 ? __ldg(t4 + (size_t)v1 * 32 + lane)
                         : make_float4(0.f, 0.f, 0.f, 0.f);
        float c0 = (lane < 16) ? g_wt[0][v0][lane] : 0.f;
        float c1 = (lane < 16 && has1) ? g_wt[0][v1][lane] : 0.f;
#pragma unroll
        for (int b = 0; b < 16; b++) {
            float k0 = __shfl_sync(FULLMASK, c0, b);
            float k1 = __shfl_sync(FULLMASK, c1, b);
            if (k0 != 0.f || k1 != 0.f) {
                float4 uu = us4[b * 32 + lane];
                float p0 = r0.x * uu.x + r0.y * uu.y + r0.z * uu.z + r0.w * uu.w;
                float p1 = r1.x * uu.x + r1.y * uu.y + r1.z * uu.z + r1.w * uu.w;
#pragma unroll
                for (int off = 16; off; off >>= 1) {
                    p0 += __shfl_xor_sync(FULLMASK, p0, off);
                    p1 += __shfl_xor_sync(FULLMASK, p1, off);
                }
                if (lane == 0) {
                    if (k0 != 0.f) g_d[v0][b] = p0;
                    if (k1 != 0.f) g_d[v1][b] = p1;
                }
            }
        }
    }
}

// ---------------------------------------------------------------------------
// logits: block per b; thread per m. logit = sum_s d[tok]; softmax over m;
// scatter prob into g_wt[1+hid][tok][b].
// ---------------------------------------------------------------------------
__global__ void __launch_bounds__(256) logits_kernel(const int* __restrict__ story,
                                                     int hid) {
    __shared__ float red[8];
    const int b = blockIdx.x, m = threadIdx.x;
    const int wid = m >> 5, lane = m & 31;

    const int4* __restrict__ tp = (const int4*)(story + ((size_t)m * BATCH + b) * SENT);
    int4 t4[16];
#pragma unroll
    for (int i = 0; i < 16; i++) t4[i] = __ldg(tp + i);

    const float* __restrict__ dp = &g_d[0][0];
    float lg = 0.f;
#pragma unroll
    for (int i = 0; i < 16; i++) {
        lg += __ldg(dp + (size_t)t4[i].x * 16 + b);
        lg += __ldg(dp + (size_t)t4[i].y * 16 + b);
        lg += __ldg(dp + (size_t)t4[i].z * 16 + b);
        lg += __ldg(dp + (size_t)t4[i].w * 16 + b);
    }

    // softmax over the 256 threads
    float mx = lg;
#pragma unroll
    for (int off = 16; off; off >>= 1)
        mx = fmaxf(mx, __shfl_xor_sync(FULLMASK, mx, off));
    if (lane == 0) red[wid] = mx;
    __syncthreads();
    mx = red[0];
#pragma unroll
    for (int i = 1; i < 8; i++) mx = fmaxf(mx, red[i]);
    __syncthreads();

    float ev = __expf(lg - mx);
    float sv = ev;
#pragma unroll
    for (int off = 16; off; off >>= 1)
        sv += __shfl_xor_sync(FULLMASK, sv, off);
    if (lane == 0) red[wid] = sv;
    __syncthreads();
    float tot = red[0];
#pragma unroll
    for (int i = 1; i < 8; i++) tot += red[i];

    const float p = ev / tot;

    // scatter prob over this sentence's tokens
    float* __restrict__ wp = &g_wt[1 + hid][0][0];
#pragma unroll
    for (int i = 0; i < 16; i++) {
        atomicAdd(wp + (size_t)t4[i].x * 16 + b, p);
        atomicAdd(wp + (size_t)t4[i].y * 16 + b, p);
        atomicAdd(wp + (size_t)t4[i].z * 16 + b, p);
        atomicAdd(wp + (size_t)t4[i].w * 16 + b, p);
    }
}

// ---------------------------------------------------------------------------
// final: out = u2 + o2 = acc0/256 + acc1 + acc2
// ---------------------------------------------------------------------------
__global__ void __launch_bounds__(128) final_kernel(float* __restrict__ out) {
    int i = blockIdx.x * 128 + threadIdx.x;
    out[i] = g_acc[0][i] * (1.f / 256.f) + g_acc[1][i] + g_acc[2][i];
}

extern "C" void kernel_launch(void* const* d_in, const int* in_sizes, int n_in,
                              void* d_out, int out_size) {
    const int*   story = (const int*)d_in[0];   // (256, 16, 64) int32
    const float* C     = (const float*)d_in[1]; // (4, 50257, 128) fp32
    float*       out   = (float*)d_out;         // (16, 128) fp32

    (void)in_sizes; (void)n_in; (void)out_size;

    const float* C1 = C + 1 * TBL;
    const float* C2 = C + 2 * TBL;
    const float* C3 = C + 3 * TBL;

    zero_kernel<<<2356, 256>>>();                 // zero wt + acc
    cnt_kernel<<<1024, 256>>>(story);             // counts

    scan_w<<<148, 256>>>(C1, 0, 0);               // u1_raw = sum cnt*C1
    scan_d<<<1184, 256>>>(C1, 0);                 // d1 = C1 . u1
    logits_kernel<<<BATCH, 256>>>(story, 0);      // prob1 -> w1

    scan_w<<<148, 256>>>(C2, 1, 1);               // o1 = sum w1*C2
    scan_d<<<1184, 256>>>(C2, 1);                 // d2 = C2 . u2
    logits_kernel<<<BATCH, 256>>>(story, 1);      // prob2 -> w2

    scan_w<<<148, 256>>>(C3, 2, 2);               // o2 = sum w2*C3
    final_kernel<<<BATCH, 128>>>(out);            // out = u2 + o2
}

// round 10
// speedup vs baseline: 1.9036x; 1.9036x over previous
#include <cuda_runtime.h>

// Problem constants
#define VOCAB 50257
#define EMB   128
#define MEM   256   // memory slots (M)
#define BATCH 16    // batch (B)
#define SENT  64    // sentence length (S)
#define TBL   ((size_t)VOCAB * EMB)
#define FULLMASK 0xffffffffu

// Static scratch:
//  g_E[0/1] : E_t[b][m][d] = sum_s C[t+1][story[m][b][s]][d]  (4.2 MB)
//  g_u1/u2  : hop states
//  g_w2     : prob2 scattered over token occurrences (padded by 1 row)
//  g_o2     : o2 accumulator
__device__ __align__(16) float g_E[2][BATCH][MEM][EMB];
__device__ __align__(16) float g_u1[BATCH][EMB];
__device__ __align__(16) float g_u2[BATCH][EMB];
__device__ __align__(16) float g_w2[VOCAB + 1][16];
__device__ __align__(16) float g_o2[BATCH * EMB];

// ---------------------------------------------------------------------------
// Gather-sum one (t,b,m) unit with one warp from the fp32 table (proven form).
// ---------------------------------------------------------------------------
__device__ __forceinline__ void gather_unit(const int* __restrict__ story,
                                            const float* __restrict__ C,
                                            int t, int b, int m, int lane) {
    const int* toks = story + ((size_t)m * BATCH + b) * SENT;
    const int tok_lo = toks[lane];
    const int tok_hi = toks[lane + 32];

    const float4* __restrict__ tab =
        (const float4*)(C + (size_t)(t + 1) * TBL);

    float4 a0 = make_float4(0.f, 0.f, 0.f, 0.f);
    float4 a1 = make_float4(0.f, 0.f, 0.f, 0.f);

#pragma unroll
    for (int s = 0; s < 32; s++) {
        int tok = __shfl_sync(FULLMASK, tok_lo, s);
        float4 v = __ldg(tab + (size_t)tok * (EMB / 4) + lane);
        a0.x += v.x; a0.y += v.y; a0.z += v.z; a0.w += v.w;
    }
#pragma unroll
    for (int s = 0; s < 32; s++) {
        int tok = __shfl_sync(FULLMASK, tok_hi, s);
        float4 v = __ldg(tab + (size_t)tok * (EMB / 4) + lane);
        a1.x += v.x; a1.y += v.y; a1.z += v.z; a1.w += v.w;
    }

    float4 acc = make_float4(a0.x + a1.x, a0.y + a1.y, a0.z + a1.z, a0.w + a1.w);
    ((float4*)g_E[t][b][m])[lane] = acc;
}

// ---------------------------------------------------------------------------
// hop0 for batch b, 256 threads: g_u1[b] = mean_m E0[b][m]
// ---------------------------------------------------------------------------
__device__ __forceinline__ void hop0_256(int b) {
    __shared__ float4 wp0[8][32];
    const int tid = threadIdx.x, w = tid >> 5, lane = tid & 31;
    const float4* __restrict__ E0 = (const float4*)g_E[0][b];

    float4 acc = make_float4(0.f, 0.f, 0.f, 0.f);
#pragma unroll 4
    for (int k = 0; k < 32; k++) {
        float4 v = E0[(size_t)(w * 32 + k) * 32 + lane];
        acc.x += v.x; acc.y += v.y; acc.z += v.z; acc.w += v.w;
    }
    wp0[w][lane] = acc;
    __syncthreads();
    if (tid < 32) {
        float4 a = wp0[0][tid];
#pragma unroll
        for (int i = 1; i < 8; i++) {
            float4 c = wp0[i][tid];
            a.x += c.x; a.y += c.y; a.z += c.z; a.w += c.w;
        }
        a.x *= (1.f / MEM); a.y *= (1.f / MEM); a.z *= (1.f / MEM); a.w *= (1.f / MEM);
        ((float4*)g_u1[b])[tid] = a;
    }
}

// ---------------------------------------------------------------------------
// logits + softmax helper: prob[m] = softmax_m( E[b][m] . u )  (256 threads)
// us: state in smem (32 float4). prob/red: smem scratch.
// ---------------------------------------------------------------------------
__device__ __forceinline__ void logits_softmax(const float4* __restrict__ Ep,
                                               const float4* us,
                                               float* prob, float* red) {
    const int tid = threadIdx.x, w = tid >> 5, lane = tid & 31;
    const int q = lane & 3, sl = lane >> 2;
#pragma unroll
    for (int pass = 0; pass < 4; pass++) {
        const int m = pass * 64 + w * 8 + sl;
        float pd = 0.f;
#pragma unroll
        for (int j = 0; j < 8; j++) {
            float4 e  = Ep[(size_t)m * 32 + q + 4 * j];
            float4 uu = us[q + 4 * j];
            pd += e.x * uu.x + e.y * uu.y + e.z * uu.z + e.w * uu.w;
        }
        pd += __shfl_xor_sync(FULLMASK, pd, 1);
        pd += __shfl_xor_sync(FULLMASK, pd, 2);
        if (q == 0) prob[m] = pd;
    }
    __syncthreads();

    float x = prob[tid];
    float mx = x;
#pragma unroll
    for (int off = 16; off; off >>= 1)
        mx = fmaxf(mx, __shfl_xor_sync(FULLMASK, mx, off));
    if (lane == 0) red[w] = mx;
    __syncthreads();
    mx = red[0];
#pragma unroll
    for (int i = 1; i < 8; i++) mx = fmaxf(mx, red[i]);
    __syncthreads();

    float ev = __expf(x - mx);
    float sv = ev;
#pragma unroll
    for (int off = 16; off; off >>= 1)
        sv += __shfl_xor_sync(FULLMASK, sv, off);
    if (lane == 0) red[w] = sv;
    __syncthreads();
    float tot = red[0];
#pragma unroll
    for (int i = 1; i < 8; i++) tot += red[i];

    prob[tid] = ev / tot;
    __syncthreads();
}

// ---------------------------------------------------------------------------
// K1: gather t0 (blocks 0..511) || zero g_w2 + g_o2 (blocks 512..611)
// ---------------------------------------------------------------------------
__global__ void __launch_bounds__(256) k1_kernel(const int* __restrict__ story,
                                                 const float* __restrict__ C) {
    if (blockIdx.x < 512) {
        const int w = blockIdx.x * 8 + (threadIdx.x >> 5);
        gather_unit(story, C, 0, w / MEM, w % MEM, threadIdx.x & 31);
    } else {
        const float4 z = make_float4(0.f, 0.f, 0.f, 0.f);
        const int i0 = (blockIdx.x - 512) * 256 + threadIdx.x;
        const int stride = 100 * 256;
        const int NW = ((VOCAB + 1) * 16) / 4;     // 201032 float4
        for (int j = i0; j < NW; j += stride) ((float4*)g_w2)[j] = z;
        for (int j = i0; j < (BATCH * EMB) / 4; j += stride) ((float4*)g_o2)[j] = z;
    }
}

// ---------------------------------------------------------------------------
// K2: hop0 (blocks 0..15) || gather t1 (blocks 16..527)
// ---------------------------------------------------------------------------
__global__ void __launch_bounds__(256) k2_kernel(const int* __restrict__ story,
                                                 const float* __restrict__ C) {
    if (blockIdx.x < 16) {
        hop0_256(blockIdx.x);
    } else {
        const int w = (blockIdx.x - 16) * 8 + (threadIdx.x >> 5);
        gather_unit(story, C, 1, w / MEM, w % MEM, threadIdx.x & 31);
    }
}

// ---------------------------------------------------------------------------
// K3: per-batch block: hop1 (u2 = u1 + attn(E0;E1)) then logits2 on E1 with
// u2, softmax, scatter prob2 into g_w2.
// ---------------------------------------------------------------------------
__global__ void __launch_bounds__(256) k3_kernel(const int* __restrict__ story) {
    __shared__ float4 us[32];
    __shared__ float4 us2[32];
    __shared__ float  prob[MEM];
    __shared__ float4 wp[8][32];
    __shared__ float  red[8];

    const int b = blockIdx.x, tid = threadIdx.x, w = tid >> 5, lane = tid & 31;
    const float4* __restrict__ E0 = (const float4*)g_E[0][b];
    const float4* __restrict__ E1 = (const float4*)g_E[1][b];

    if (tid < 32) us[tid] = ((const float4*)g_u1[b])[tid];
    __syncthreads();

    // --- hop1: prob1 = softmax(E0 . u1) ---
    logits_softmax(E0, us, prob, red);

    // --- o1 = sum_m prob1[m] * E1[b][m];  u2 = u1 + o1 ---
    {
        float4 acc = make_float4(0.f, 0.f, 0.f, 0.f);
#pragma unroll 4
        for (int k = 0; k < 32; k++) {
            const int mm = w * 32 + k;
            float p = prob[mm];
            float4 v = E1[(size_t)mm * 32 + lane];
            acc.x += p * v.x; acc.y += p * v.y; acc.z += p * v.z; acc.w += p * v.w;
        }
        wp[w][lane] = acc;
        __syncthreads();
        if (tid < 32) {
            float4 a = wp[0][tid];
#pragma unroll
            for (int i = 1; i < 8; i++) {
                float4 c = wp[i][tid];
                a.x += c.x; a.y += c.y; a.z += c.z; a.w += c.w;
            }
            float4 uu = us[tid];
            a.x += uu.x; a.y += uu.y; a.z += uu.z; a.w += uu.w;
            us2[tid] = a;
            ((float4*)g_u2[b])[tid] = a;
        }
        __syncthreads();
    }

    // --- logits2: prob2 = softmax(E1 . u2) ---
    logits_softmax(E1, us2, prob, red);

    // --- scatter prob2 over this sentence's tokens into g_w2 ---
    {
        const int m = tid;
        const float p = prob[m];
        const int4* __restrict__ tp =
            (const int4*)(story + ((size_t)m * BATCH + b) * SENT);
#pragma unroll
        for (int i = 0; i < 16; i++) {
            int4 t = __ldg(tp + i);
            atomicAdd(&g_w2[t.x][b], p);
            atomicAdd(&g_w2[t.y][b], p);
            atomicAdd(&g_w2[t.z][b], p);
            atomicAdd(&g_w2[t.w][b], p);
        }
    }
}

// ---------------------------------------------------------------------------
// K4: o2[b][:] = sum_v w2[v][b] * C3[v][:]. Warp per 2 rows, grid-stride,
// 4 CTAs/SM. Weight pair loaded as one coalesced 128B line; warp-uniform
// zero-skip (~72% of (v,b) pairs are zero).
// ---------------------------------------------------------------------------
__global__ void __launch_bounds__(256) k4_kernel(const float* __restrict__ C) {
    const int wid = threadIdx.x >> 5, lane = threadIdx.x & 31;
    const int gw = blockIdx.x * 8 + wid, nw = gridDim.x * 8;
    const float4* __restrict__ t4 = (const float4*)(C + 3 * TBL);

    float4 acc[16];
#pragma unroll
    for (int b = 0; b < 16; b++) acc[b] = make_float4(0.f, 0.f, 0.f, 0.f);

    const int NP = (VOCAB + 1) / 2;            // 25129 row-pairs
    for (int p = gw; p < NP; p += nw) {
        const int v0 = 2 * p, v1 = v0 + 1;
        const bool has1 = (v1 < VOCAB);
        // one 128B line: lanes 0..15 = w2[v0][b], lanes 16..31 = w2[v1][b]
        float wv = ((const float*)g_w2[v0])[lane];
        float4 r0 = __ldg(t4 + (size_t)v0 * 32 + lane);
        float4 r1 = has1 ? __ldg(t4 + (size_t)v1 * 32 + lane)
                         : make_float4(0.f, 0.f, 0.f, 0.f);
#pragma unroll
        for (int b = 0; b < 16; b++) {
            float c0 = __shfl_sync(FULLMASK, wv, b);
            float c1 = __shfl_sync(FULLMASK, wv, 16 + b);
            if (c0 != 0.f) {
                acc[b].x += c0 * r0.x; acc[b].y += c0 * r0.y;
                acc[b].z += c0 * r0.z; acc[b].w += c0 * r0.w;
            }
            if (c1 != 0.f) {
                acc[b].x += c1 * r1.x; acc[b].y += c1 * r1.y;
                acc[b].z += c1 * r1.z; acc[b].w += c1 * r1.w;
            }
        }
    }

    // block reduction (two 8-b rounds), then atomics into g_o2
    __shared__ float4 sred[8][8][32];
#pragma unroll
    for (int r = 0; r < 2; r++) {
#pragma unroll
        for (int i = 0; i < 8; i++) sred[wid][i][lane] = acc[r * 8 + i];
        __syncthreads();
        {
            const int bi = threadIdx.x >> 5, ln = threadIdx.x & 31;
            float4 s = sred[0][bi][ln];
#pragma unroll
            for (int k = 1; k < 8; k++) {
                float4 c = sred[k][bi][ln];
                s.x += c.x; s.y += c.y; s.z += c.z; s.w += c.w;
            }
            float* dst = &g_o2[(r * 8 + bi) * EMB + ln * 4];
            atomicAdd(dst + 0, s.x); atomicAdd(dst + 1, s.y);
            atomicAdd(dst + 2, s.z); atomicAdd(dst + 3, s.w);
        }
        __syncthreads();
    }
}

// ---------------------------------------------------------------------------
// K5: out = u2 + o2
// ---------------------------------------------------------------------------
__global__ void __launch_bounds__(128) k5_kernel(float* __restrict__ out) {
    int i = blockIdx.x * 128 + threadIdx.x;
    out[i] = ((const float*)g_u2)[i] + g_o2[i];
}

extern "C" void kernel_launch(void* const* d_in, const int* in_sizes, int n_in,
                              void* d_out, int out_size) {
    const int*   story = (const int*)d_in[0];   // (256, 16, 64) int32
    const float* C     = (const float*)d_in[1]; // (4, 50257, 128) fp32
    float*       out   = (float*)d_out;         // (16, 128) fp32

    (void)in_sizes; (void)n_in; (void)out_size;

    k1_kernel<<<612, 256>>>(story, C);   // gather t0 || zero w2/o2
    k2_kernel<<<528, 256>>>(story, C);   // hop0 || gather t1
    k3_kernel<<<BATCH, 256>>>(story);    // hop1 + logits2 + scatter
    k4_kernel<<<592, 256>>>(C);          // o2 = scan(C3, w2)
    k5_kernel<<<BATCH, 128>>>(out);      // out = u2 + o2
}

// round 11
// speedup vs baseline: 3.9193x; 2.0589x over previous
#include <cuda_runtime.h>

// Problem constants
#define VOCAB 50257
#define EMB   128
#define MEM   256   // memory slots (M)
#define BATCH 16    // batch (B)
#define SENT  64    // sentence length (S)
#define TBL   ((size_t)VOCAB * EMB)
#define FULLMASK 0xffffffffu

// Static scratch:
//  g_E[t][b][m][d] = sum_s C[t+1][story[m][b][s]][d]   (6.3 MB)
//  g_u1[b]         = hop-0 state
//  g_prob[b][m]    = prob2 (attention weights of hop 2)
__device__ __align__(16) float g_E[3][BATCH][MEM][EMB];
__device__ __align__(16) float g_u1[BATCH][EMB];
__device__ __align__(16) float g_prob[BATCH][MEM];

// ---------------------------------------------------------------------------
// Gather-sum one (t,b,m) unit with one warp from the fp32 table.
// 64 token rows x 512B, coalesced LDG.128; measured at the LTS cap.
// ---------------------------------------------------------------------------
__device__ __forceinline__ void gather_unit(const int* __restrict__ story,
                                            const float* __restrict__ C,
                                            int t, int b, int m, int lane) {
    const int* toks = story + ((size_t)m * BATCH + b) * SENT;
    const int tok_lo = toks[lane];
    const int tok_hi = toks[lane + 32];

    const float4* __restrict__ tab =
        (const float4*)(C + (size_t)(t + 1) * TBL);

    float4 a0 = make_float4(0.f, 0.f, 0.f, 0.f);
    float4 a1 = make_float4(0.f, 0.f, 0.f, 0.f);

#pragma unroll
    for (int s = 0; s < 32; s++) {
        int tok = __shfl_sync(FULLMASK, tok_lo, s);
        float4 v = __ldg(tab + (size_t)tok * (EMB / 4) + lane);
        a0.x += v.x; a0.y += v.y; a0.z += v.z; a0.w += v.w;
    }
#pragma unroll
    for (int s = 0; s < 32; s++) {
        int tok = __shfl_sync(FULLMASK, tok_hi, s);
        float4 v = __ldg(tab + (size_t)tok * (EMB / 4) + lane);
        a1.x += v.x; a1.y += v.y; a1.z += v.z; a1.w += v.w;
    }

    float4 acc = make_float4(a0.x + a1.x, a0.y + a1.y, a0.z + a1.z, a0.w + a1.w);
    ((float4*)g_E[t][b][m])[lane] = acc;
}

// ---------------------------------------------------------------------------
// hop0 for batch b, 256 threads: g_u1[b] = mean_m E0[b][m]
// ---------------------------------------------------------------------------
__device__ __forceinline__ void hop0_256(int b) {
    __shared__ float4 wp0[8][32];
    const int tid = threadIdx.x, w = tid >> 5, lane = tid & 31;
    const float4* __restrict__ E0 = (const float4*)g_E[0][b];

    float4 acc = make_float4(0.f, 0.f, 0.f, 0.f);
#pragma unroll 4
    for (int k = 0; k < 32; k++) {
        float4 v = E0[(size_t)(w * 32 + k) * 32 + lane];
        acc.x += v.x; acc.y += v.y; acc.z += v.z; acc.w += v.w;
    }
    wp0[w][lane] = acc;
    __syncthreads();
    if (tid < 32) {
        float4 a = wp0[0][tid];
#pragma unroll
        for (int i = 1; i < 8; i++) {
            float4 c = wp0[i][tid];
            a.x += c.x; a.y += c.y; a.z += c.z; a.w += c.w;
        }
        a.x *= (1.f / MEM); a.y *= (1.f / MEM); a.z *= (1.f / MEM); a.w *= (1.f / MEM);
        ((float4*)g_u1[b])[tid] = a;
    }
}

// ---------------------------------------------------------------------------
// logits + softmax: prob[m] = softmax_m( Ep[m] . us )  (256 threads)
// ---------------------------------------------------------------------------
__device__ __forceinline__ void logits_softmax(const float4* __restrict__ Ep,
                                               const float4* us,
                                               float* prob, float* red) {
    const int tid = threadIdx.x, w = tid >> 5, lane = tid & 31;
    const int q = lane & 3, sl = lane >> 2;
#pragma unroll
    for (int pass = 0; pass < 4; pass++) {
        const int m = pass * 64 + w * 8 + sl;
        float pd = 0.f;
#pragma unroll
        for (int j = 0; j < 8; j++) {
            float4 e  = Ep[(size_t)m * 32 + q + 4 * j];
            float4 uu = us[q + 4 * j];
            pd += e.x * uu.x + e.y * uu.y + e.z * uu.z + e.w * uu.w;
        }
        pd += __shfl_xor_sync(FULLMASK, pd, 1);
        pd += __shfl_xor_sync(FULLMASK, pd, 2);
        if (q == 0) prob[m] = pd;
    }
    __syncthreads();

    float x = prob[tid];
    float mx = x;
#pragma unroll
    for (int off = 16; off; off >>= 1)
        mx = fmaxf(mx, __shfl_xor_sync(FULLMASK, mx, off));
    if (lane == 0) red[w] = mx;
    __syncthreads();
    mx = red[0];
#pragma unroll
    for (int i = 1; i < 8; i++) mx = fmaxf(mx, red[i]);
    __syncthreads();

    float ev = __expf(x - mx);
    float sv = ev;
#pragma unroll
    for (int off = 16; off; off >>= 1)
        sv += __shfl_xor_sync(FULLMASK, sv, off);
    if (lane == 0) red[w] = sv;
    __syncthreads();
    float tot = red[0];
#pragma unroll
    for (int i = 1; i < 8; i++) tot += red[i];

    prob[tid] = ev / tot;
    __syncthreads();
}

// ---------------------------------------------------------------------------
// K1: gather t0. 512 blocks x 8 warps.
// ---------------------------------------------------------------------------
__global__ void __launch_bounds__(256) k1_kernel(const int* __restrict__ story,
                                                 const float* __restrict__ C) {
    const int w = blockIdx.x * 8 + (threadIdx.x >> 5);
    gather_unit(story, C, 0, w / MEM, w % MEM, threadIdx.x & 31);
}

// ---------------------------------------------------------------------------
// K2: hop0 (blocks 0..15) || gather t1 (blocks 16..527)
// ---------------------------------------------------------------------------
__global__ void __launch_bounds__(256) k2_kernel(const int* __restrict__ story,
                                                 const float* __restrict__ C) {
    if (blockIdx.x < 16) {
        hop0_256(blockIdx.x);
    } else {
        const int w = (blockIdx.x - 16) * 8 + (threadIdx.x >> 5);
        gather_unit(story, C, 1, w / MEM, w % MEM, threadIdx.x & 31);
    }
}

// ---------------------------------------------------------------------------
// K3: blocks 0..15: hop1 (u2 = u1 + attn(E0;E1)), write out[b]=u2, then
//     logits2 = softmax(E1 . u2) -> g_prob[b].
//     blocks 16..527: gather t2.
// ---------------------------------------------------------------------------
__global__ void __launch_bounds__(256) k3_kernel(const int* __restrict__ story,
                                                 const float* __restrict__ C,
                                                 float* __restrict__ out) {
    if (blockIdx.x >= 16) {
        const int w = (blockIdx.x - 16) * 8 + (threadIdx.x >> 5);
        gather_unit(story, C, 2, w / MEM, w % MEM, threadIdx.x & 31);
        return;
    }

    __shared__ float4 us[32];
    __shared__ float4 us2[32];
    __shared__ float  prob[MEM];
    __shared__ float4 wp[8][32];
    __shared__ float  red[8];

    const int b = blockIdx.x, tid = threadIdx.x, w = tid >> 5, lane = tid & 31;
    const float4* __restrict__ E0 = (const float4*)g_E[0][b];
    const float4* __restrict__ E1 = (const float4*)g_E[1][b];

    if (tid < 32) us[tid] = ((const float4*)g_u1[b])[tid];
    __syncthreads();

    // hop1 attention: prob1 = softmax(E0 . u1)
    logits_softmax(E0, us, prob, red);

    // o1 = sum_m prob1[m] * E1[b][m]; u2 = u1 + o1; out[b] = u2
    {
        float4 acc = make_float4(0.f, 0.f, 0.f, 0.f);
#pragma unroll 4
        for (int k = 0; k < 32; k++) {
            const int mm = w * 32 + k;
            float p = prob[mm];
            float4 v = E1[(size_t)mm * 32 + lane];
            acc.x += p * v.x; acc.y += p * v.y; acc.z += p * v.z; acc.w += p * v.w;
        }
        wp[w][lane] = acc;
        __syncthreads();
        if (tid < 32) {
            float4 a = wp[0][tid];
#pragma unroll
            for (int i = 1; i < 8; i++) {
                float4 c = wp[i][tid];
                a.x += c.x; a.y += c.y; a.z += c.z; a.w += c.w;
            }
            float4 uu = us[tid];
            a.x += uu.x; a.y += uu.y; a.z += uu.z; a.w += uu.w;
            us2[tid] = a;
            ((float4*)out)[(size_t)b * 32 + tid] = a;   // out = u2 (K4 adds o2)
        }
        __syncthreads();
    }

    // logits2: prob2 = softmax(E1 . u2) -> g_prob[b]
    logits_softmax(E1, us2, prob, red);
    g_prob[b][tid] = prob[tid];
}

// ---------------------------------------------------------------------------
// K4: out[b] += sum_m prob2[m] * E2[b][m], split 8 blocks per batch
// (32 slots each) for a short, high-MLP tail. atomicAdd accumulate.
// ---------------------------------------------------------------------------
__global__ void __launch_bounds__(256) k4_kernel(float* __restrict__ out) {
    __shared__ float4 wp[8][32];
    const int b = blockIdx.x >> 3, chunk = blockIdx.x & 7;
    const int tid = threadIdx.x, w = tid >> 5, lane = tid & 31;
    const float4* __restrict__ E2 = (const float4*)g_E[2][b];

    float4 acc = make_float4(0.f, 0.f, 0.f, 0.f);
#pragma unroll
    for (int k = 0; k < 4; k++) {
        const int m = chunk * 32 + w * 4 + k;
        float p = __ldg(&g_prob[b][m]);
        float4 v = E2[(size_t)m * 32 + lane];
        acc.x += p * v.x; acc.y += p * v.y; acc.z += p * v.z; acc.w += p * v.w;
    }
    wp[w][lane] = acc;
    __syncthreads();
    if (tid < 32) {
        float4 a = wp[0][tid];
#pragma unroll
        for (int i = 1; i < 8; i++) {
            float4 c = wp[i][tid];
            a.x += c.x; a.y += c.y; a.z += c.z; a.w += c.w;
        }
        float* dst = out + (size_t)b * EMB + tid * 4;
        atomicAdd(dst + 0, a.x); atomicAdd(dst + 1, a.y);
        atomicAdd(dst + 2, a.z); atomicAdd(dst + 3, a.w);
    }
}

extern "C" void kernel_launch(void* const* d_in, const int* in_sizes, int n_in,
                              void* d_out, int out_size) {
    const int*   story = (const int*)d_in[0];   // (256, 16, 64) int32
    const float* C     = (const float*)d_in[1]; // (4, 50257, 128) fp32
    float*       out   = (float*)d_out;         // (16, 128) fp32

    (void)in_sizes; (void)n_in; (void)out_size;

    k1_kernel<<<512, 256>>>(story, C);          // gather t0
    k2_kernel<<<528, 256>>>(story, C);          // hop0 || gather t1
    k3_kernel<<<528, 256>>>(story, C, out);     // hop1+logits2 || gather t2
    k4_kernel<<<128, 256>>>(out);               // out += weighted-sum(E2, prob2)
}